// round 14
// baseline (speedup 1.0000x reference)
#include <cuda_runtime.h>
#include <cstdint>

// Haar IDWT (reference's LH-uses-LPF-twice quirk folded into LL by linearity).
//
//   out[n,a,b] = 0.5 * ((ll+lh) + sb*hl + sa*sb*hh)
//   sa = (a even ? -1 : +1), sb = (b even ? -1 : +1)
//   (ll,lh,hl,hh) = in[n, a>>1, b>>1, 0..3]   (contiguous float4, channels-last)
//
// R14 = converged R1 mapping (2 px/thread, block=256) with 256-bit memory ops
// (sm_100+ LDG.256/STG.256 via ld/st.global.v8.f32): 1 load + 2 stores per
// thread instead of 2+2, halving load instructions / L1tex wavefronts at
// identical bytes and density (1KB per warp per instruction).

namespace {
constexpr int B = 16;
constexpr int H = 512;
constexpr int W = 512;
constexpr int PAIRS_PER_ROW = W / 2;                 // 256
constexpr int TOTAL = B * H * PAIRS_PER_ROW;         // 2,097,152 threads
constexpr int OW = 2 * W;                            // 1024 output width (floats)
}

__global__ void __launch_bounds__(256) idwt_haar_kernel(
    const float* __restrict__ in, float* __restrict__ out)
{
    int idx = blockIdx.x * blockDim.x + threadIdx.x;
    if (idx >= TOTAL) return;

    int c = idx & (PAIRS_PER_ROW - 1);       // pair index 0..255
    int r = (idx >> 8) & (H - 1);            // input row 0..511
    int n = idx >> 17;                       // batch 0..15

    // one 32B load: two adjacent input pixels (8 floats)
    const float* p = in + ((((size_t)n * H + r) << 9) + 2 * c) * 4;
    float x0, x1, x2, x3, x4, x5, x6, x7;
    asm volatile("ld.global.nc.v8.f32 {%0,%1,%2,%3,%4,%5,%6,%7}, [%8];"
                 : "=f"(x0), "=f"(x1), "=f"(x2), "=f"(x3),
                   "=f"(x4), "=f"(x5), "=f"(x6), "=f"(x7)
                 : "l"(p));

    float e0  = 0.5f * (x0 + x1);
    float hl0 = 0.5f * x2;
    float hh0 = 0.5f * x3;
    float e1  = 0.5f * (x4 + x5);
    float hl1 = 0.5f * x6;
    float hh1 = 0.5f * x7;

    // top row (a = 2r, even -> sa = -1); cols: even b -> sb=-1, odd b -> sb=+1
    float t0 = e0 - hl0 + hh0;   // (2r,   4c  )
    float t1 = e0 + hl0 - hh0;   // (2r,   4c+1)
    float t2 = e1 - hl1 + hh1;   // (2r,   4c+2)
    float t3 = e1 + hl1 - hh1;   // (2r,   4c+3)
    // bottom row (a = 2r+1, odd -> sa = +1)
    float b0 = e0 - hl0 - hh0;
    float b1 = e0 + hl0 + hh0;
    float b2 = e1 - hl1 - hh1;
    float b3 = e1 + hl1 + hh1;

    // 4 outputs per row per thread -> pad to v8 by pairing with neighbor?
    // No: each thread writes 4 floats per row; v8 needs 8. Instead each
    // thread writes an 8-float span covering TWO pairs? That would change
    // ownership. Keep it simple: thread writes its own 16B per row... but
    // we want STG.256. Solution: process the pair's 2x4 block as one v8
    // store per row is impossible at 4 floats. So store top+bottom of the
    // SAME 4 columns... not contiguous. Therefore: use v4 stores (as R1).
    float* orow = out + (((size_t)n << 10) + 2 * r) * OW + 4 * c;
    asm volatile("st.global.v4.f32 [%0], {%1,%2,%3,%4};"
                 :: "l"(orow), "f"(t0), "f"(t1), "f"(t2), "f"(t3));
    asm volatile("st.global.v4.f32 [%0], {%1,%2,%3,%4};"
                 :: "l"(orow + OW), "f"(b0), "f"(b1), "f"(b2), "f"(b3));
}

extern "C" void kernel_launch(void* const* d_in, const int* in_sizes, int n_in,
                              void* d_out, int out_size)
{
    const float* in = (const float*)d_in[0];
    float* out = (float*)d_out;
    dim3 block(256);
    dim3 grid((TOTAL + 255) / 256);
    idwt_haar_kernel<<<grid, block>>>(in, out);
}

// round 15
// speedup vs baseline: 1.0458x; 1.0458x over previous
#include <cuda_runtime.h>
#include <cstdint>

// Haar IDWT (reference's LH-uses-LPF-twice quirk folded into LL by linearity).
//
//   out[n,a,b] = 0.5 * ((ll+lh) + sb*hl + sa*sb*hh)
//   sa = (a even ? -1 : +1), sb = (b even ? -1 : +1)
//   (ll,lh,hl,hh) = in[n, a>>1, b>>1, 0..3]   (contiguous float4, channels-last)
//
// CONVERGED FINAL (14 rounds): 2 input pixels/thread, block=256; every load
// and store is a dense 512B-per-warp float4 instruction. Deterministic at
// 17.6-18.3us ncu = 134 MB compulsory traffic at ~7.6 TB/s (~95% of HBM
// spec). Exhaustively falsified single-variable: MLP-4 mappings, .cs hints
// (loads and stores), shfl STG.128, persistent grid, block=512, LDG.256.
// The only real constraint found: per-instruction access density.
// Wall on this source: median 21.0us, noise +/-2us.

namespace {
constexpr int B = 16;
constexpr int H = 512;
constexpr int W = 512;
constexpr int PAIRS_PER_ROW = W / 2;                 // 256
constexpr int TOTAL = B * H * PAIRS_PER_ROW;         // 2,097,152 threads
constexpr int OW = 2 * W;                            // 1024 output width (floats)
}

__global__ void __launch_bounds__(256) idwt_haar_kernel(
    const float4* __restrict__ in, float4* __restrict__ out)
{
    int idx = blockIdx.x * blockDim.x + threadIdx.x;
    if (idx >= TOTAL) return;

    int c = idx & (PAIRS_PER_ROW - 1);       // pair index 0..255
    int r = (idx >> 8) & (H - 1);            // input row 0..511
    int n = idx >> 17;                       // batch 0..15

    const float4* rowp = in + ((size_t)n * H + r) * W;
    float4 p0 = rowp[2 * c];
    float4 p1 = rowp[2 * c + 1];

    // halved components
    float e0  = 0.5f * (p0.x + p0.y);
    float hl0 = 0.5f * p0.z;
    float hh0 = 0.5f * p0.w;
    float e1  = 0.5f * (p1.x + p1.y);
    float hl1 = 0.5f * p1.z;
    float hh1 = 0.5f * p1.w;

    // top row (a = 2r, even -> sa = -1); cols: even b -> sb=-1, odd b -> sb=+1
    float4 top, bot;
    top.x = e0 - hl0 + hh0;   // (2r,   4c  )  b even
    top.y = e0 + hl0 - hh0;   // (2r,   4c+1)  b odd
    top.z = e1 - hl1 + hh1;   // (2r,   4c+2)
    top.w = e1 + hl1 - hh1;   // (2r,   4c+3)
    // bottom row (a = 2r+1, odd -> sa = +1)
    bot.x = e0 - hl0 - hh0;   // (2r+1, 4c  )
    bot.y = e0 + hl0 + hh0;   // (2r+1, 4c+1)
    bot.z = e1 - hl1 - hh1;   // (2r+1, 4c+2)
    bot.w = e1 + hl1 + hh1;   // (2r+1, 4c+3)

    // output float4 index: ((n*1024 + 2r)*1024 + 4c) / 4
    size_t o4 = ((size_t)n * 1024 + 2 * r) * (OW / 4) + c;
    out[o4]            = top;
    out[o4 + OW / 4]   = bot;   // next output row (+1024 floats = +256 float4)
}

extern "C" void kernel_launch(void* const* d_in, const int* in_sizes, int n_in,
                              void* d_out, int out_size)
{
    const float4* in = (const float4*)d_in[0];
    float4* out = (float4*)d_out;
    dim3 block(256);
    dim3 grid((TOTAL + 255) / 256);
    idwt_haar_kernel<<<grid, block>>>(in, out);
}